// round 10
// baseline (speedup 1.0000x reference)
#include <cuda_runtime.h>
#include <cuda_bf16.h>
#include <math.h>
#include <stdint.h>

// Problem dims (fixed)
#define BB   4
#define DD   512
#define LL   4096
#define NC1  1168
#define NLBL 8929

#define SCALE_INV 0.044194173824159216f  // 1/sqrt(512)

#define KC 32   // K elements per chunk

// gemm_tc smem: 3-stage, tiles 128x32 bf16 = 8KB each
#define S_AH 0
#define S_AL 24576
#define S_BH 49152
#define S_BL 73728
#define SM_TOTAL 98304

// gemm_ca smem: A fp32 tiles 128x32 f32 = 16KB x3, B pair 8KB x3 x2
#define CA_AF 0
#define CA_BH 49152
#define CA_BL 73728

typedef __nv_bfloat16 bf16;

// ---------------- device scratch ----------------
__device__ bf16  g_Hthi [(size_t)BB * LL * DD];
__device__ bf16  g_Htlo [(size_t)BB * LL * DD];
__device__ bf16  g_Khi  [(size_t)BB * LL * DD];     // [B, L, d]
__device__ bf16  g_Klo  [(size_t)BB * LL * DD];
__device__ bf16  g_Vthi [(size_t)BB * DD * LL];     // [B, d, L]
__device__ bf16  g_Vtlo [(size_t)BB * DD * LL];
__device__ float g_E1   [(size_t)BB * NC1 * LL];    // [B, C1, L] logits -> probs
__device__ float g_C1   [(size_t)BB * NC1 * DD];    // [B, C1, d]
__device__ bf16  g_Q2bhi[(size_t)BB * NLBL * DD];
__device__ bf16  g_Q2blo[(size_t)BB * NLBL * DD];
__device__ bf16  g_Wkhi [(size_t)DD * DD];
__device__ bf16  g_Wklo [(size_t)DD * DD];
__device__ bf16  g_Wvhi [(size_t)DD * DD];
__device__ bf16  g_Wvlo [(size_t)DD * DD];
__device__ bf16  g_Q1hi [(size_t)NC1 * DD];
__device__ bf16  g_Q1lo [(size_t)NC1 * DD];

// ---------------- helpers ----------------
__device__ __forceinline__ uint32_t smem_u32(const void* p) {
    uint32_t a;
    asm("{ .reg .u64 t; cvta.to.shared.u64 t, %1; cvt.u32.u64 %0, t; }" : "=r"(a) : "l"(p));
    return a;
}
__device__ __forceinline__ void cp16(uint32_t dst, const void* src, bool pred) {
    int sz = pred ? 16 : 0;
    asm volatile("cp.async.cg.shared.global [%0], [%1], 16, %2;"
                 :: "r"(dst), "l"(src), "r"(sz));
}
__device__ __forceinline__ void cp_commit() {
    asm volatile("cp.async.commit_group;" ::: "memory");
}
__device__ __forceinline__ void ldsm4(uint32_t* r, uint32_t addr) {
    asm volatile("ldmatrix.sync.aligned.m8n8.x4.shared.b16 {%0,%1,%2,%3}, [%4];"
                 : "=r"(r[0]), "=r"(r[1]), "=r"(r[2]), "=r"(r[3]) : "r"(addr));
}
__device__ __forceinline__ void mma_bf16(float* d, const uint32_t* a, const uint32_t* b) {
    asm volatile(
        "mma.sync.aligned.m16n8k16.row.col.f32.bf16.bf16.f32 "
        "{%0,%1,%2,%3}, {%4,%5,%6,%7}, {%8,%9}, {%0,%1,%2,%3};"
        : "+f"(d[0]), "+f"(d[1]), "+f"(d[2]), "+f"(d[3])
        : "r"(a[0]), "r"(a[1]), "r"(a[2]), "r"(a[3]), "r"(b[0]), "r"(b[1]));
}
__device__ __forceinline__ void bsplit(float x, bf16& h, bf16& l) {
    h = __float2bfloat16_rn(x);
    l = __float2bfloat16_rn(x - __bfloat162float(h));
}
__device__ __forceinline__ float eluf(float x) { return x > 0.0f ? x : expm1f(x); }

// pack float2 -> bf16x2 hi, return hi floats for lo computation
__device__ __forceinline__ uint32_t pack_hi(float2 v, float2& hf) {
    __nv_bfloat162 h = __float22bfloat162_rn(v);
    hf.x = __bfloat162float(h.x);
    hf.y = __bfloat162float(h.y);
    return *(uint32_t*)&h;
}
__device__ __forceinline__ uint32_t pack_lo(float2 v, float2 hf) {
    __nv_bfloat162 l = __float22bfloat162_rn(make_float2(v.x - hf.x, v.y - hf.y));
    return *(uint32_t*)&l;
}

// =====================================================================
// 3xBF16 mma.sync NT GEMM (round-7 mainloop, UNCHANGED).
// A, B pre-split bf16 hi/lo, K-major.
// mode 0: split(elu(acc+bias[n])) -> Chi/Clo[m*ldc+n]
// mode 1: split(elu(acc+bias[n])) -> Chi/Clo[n*ldc+m]  (transposed)
// mode 2: Cf[m*ldc+n] = alpha * acc                    (fp32)
// =====================================================================
__global__ void __launch_bounds__(256, 2) gemm_tc(
    const bf16* __restrict__ Ahi, const bf16* __restrict__ Alo,
    const bf16* __restrict__ Bhi, const bf16* __restrict__ Blo,
    float* __restrict__ Cf, bf16* __restrict__ Chi, bf16* __restrict__ Clo,
    const float* __restrict__ bias,
    int M, int K, int lda, int ldb, int ldc,
    size_t sA, size_t sB, size_t sC, float alpha, int mode)
{
    extern __shared__ char smem[];
    const uint32_t sbase = smem_u32(smem);

    const int tid  = threadIdx.x;
    const int wid  = tid >> 5;
    const int lane = tid & 31;
    const int g    = lane >> 3;
    const int r    = lane & 7;
    const int warp_m = wid & 3;
    const int warp_n = wid >> 2;

    const bf16* Ah = Ahi + (size_t)blockIdx.z * sA;
    const bf16* Al = Alo + (size_t)blockIdx.z * sA;
    const bf16* Bh = Bhi + (size_t)blockIdx.z * sB;
    const bf16* Bl = Blo + (size_t)blockIdx.z * sB;
    const int m0 = blockIdx.y * 128;
    const int n0 = blockIdx.x * 128;

    uint32_t aoff[2], aswz[2], boff[4], bswz[4];
    #pragma unroll
    for (int mt = 0; mt < 2; ++mt) {
        int row = warp_m * 32 + mt * 16 + (g & 1) * 8 + r;
        aoff[mt] = (uint32_t)row * 64;
        aswz[mt] = (uint32_t)((row >> 1) & 3);
    }
    const uint32_t aq = (uint32_t)(g >> 1);
    #pragma unroll
    for (int p = 0; p < 4; ++p) {
        int row = warp_n * 64 + p * 16 + (g >> 1) * 8 + r;
        boff[p] = (uint32_t)row * 64;
        bswz[p] = (uint32_t)((row >> 1) & 3);
    }
    const uint32_t bq = (uint32_t)(g & 1);

    const int sr0 = tid >> 2;
    const int sq  = tid & 3;

    float acc[2][8][4];
    #pragma unroll
    for (int mt = 0; mt < 2; ++mt)
        #pragma unroll
        for (int nt = 0; nt < 8; ++nt)
            #pragma unroll
            for (int c = 0; c < 4; ++c) acc[mt][nt][c] = 0.0f;

    const int nc = K >> 5;

#define STAGE(BUF, K0)                                                           \
    {                                                                            \
        const uint32_t _bo = (uint32_t)(BUF) * 8192u;                            \
        _Pragma("unroll")                                                        \
        for (int q = 0; q < 2; ++q) {                                            \
            int row = sr0 + q * 64;                                              \
            uint32_t d = (uint32_t)row * 64 + ((sq ^ ((row >> 1) & 3)) << 4);    \
            int m = m0 + row;                                                    \
            size_t ao = (size_t)(m < M ? m : 0) * lda + (K0) + sq * 8;           \
            cp16(sbase + S_AH + _bo + d, Ah + ao, m < M);                        \
            cp16(sbase + S_AL + _bo + d, Al + ao, m < M);                        \
            size_t bo2 = (size_t)(n0 + row) * ldb + (K0) + sq * 8;               \
            cp16(sbase + S_BH + _bo + d, Bh + bo2, true);                        \
            cp16(sbase + S_BL + _bo + d, Bl + bo2, true);                        \
        }                                                                        \
        cp_commit();                                                             \
    }

    STAGE(0, 0)
    STAGE(1, KC)

    int bi = 0;
    for (int i = 0; i < nc; ++i) {
        asm volatile("cp.async.wait_group 1;" ::: "memory");
        __syncthreads();

        const uint32_t bo  = (uint32_t)bi * 8192u;
        const uint32_t ahb = sbase + S_AH + bo;
        const uint32_t alb = sbase + S_AL + bo;
        const uint32_t bhb = sbase + S_BH + bo;
        const uint32_t blb = sbase + S_BL + bo;

        #pragma unroll
        for (int ks = 0; ks < 2; ++ks) {
            const uint32_t qa = (uint32_t)(ks * 2) + aq;
            const uint32_t qb = (uint32_t)(ks * 2) + bq;
            uint32_t ah[2][4], al[2][4];
            #pragma unroll
            for (int mt = 0; mt < 2; ++mt) {
                const uint32_t o = aoff[mt] + ((qa ^ aswz[mt]) << 4);
                ldsm4(ah[mt], ahb + o);
                ldsm4(al[mt], alb + o);
            }
            #pragma unroll
            for (int p = 0; p < 4; ++p) {
                uint32_t bhf[4], blf[4];
                const uint32_t o = boff[p] + ((qb ^ bswz[p]) << 4);
                ldsm4(bhf, bhb + o);
                ldsm4(blf, blb + o);
                #pragma unroll
                for (int h2 = 0; h2 < 2; ++h2) {
                    const int nt = p * 2 + h2;
                    #pragma unroll
                    for (int mt = 0; mt < 2; ++mt) {
                        mma_bf16(acc[mt][nt], ah[mt], &bhf[h2 * 2]);  // hi*hi
                        mma_bf16(acc[mt][nt], ah[mt], &blf[h2 * 2]);  // hi*lo
                        mma_bf16(acc[mt][nt], al[mt], &bhf[h2 * 2]);  // lo*hi
                    }
                }
            }
        }

        if (i + 2 < nc) {
            int nb = bi + 2; if (nb >= 3) nb -= 3;
            const int k0 = (i + 2) * KC;
            STAGE(nb, k0)
        } else {
            cp_commit();
        }
        if (++bi == 3) bi = 0;
    }
#undef STAGE

    // ---- epilogue ----
    const int rq = lane >> 2;
    const int cq = (lane & 3) * 2;
    float* C  = Cf  ? Cf  + (size_t)blockIdx.z * sC : (float*)0;
    bf16*  CH = Chi ? Chi + (size_t)blockIdx.z * sC : (bf16*)0;
    bf16*  CL = Clo ? Clo + (size_t)blockIdx.z * sC : (bf16*)0;
    #pragma unroll
    for (int mt = 0; mt < 2; ++mt) {
        #pragma unroll
        for (int nt = 0; nt < 8; ++nt) {
            const int row = m0 + warp_m * 32 + mt * 16 + rq;
            const int col = n0 + warp_n * 64 + nt * 8 + cq;
            const float* a4 = acc[mt][nt];
            if (mode == 2) {
                if (row < M)
                    *(float2*)(C + (size_t)row * ldc + col) =
                        make_float2(alpha * a4[0], alpha * a4[1]);
                if (row + 8 < M)
                    *(float2*)(C + (size_t)(row + 8) * ldc + col) =
                        make_float2(alpha * a4[2], alpha * a4[3]);
            } else {
                const float b0 = bias[col], b1 = bias[col + 1];
                bf16 h0, l0, h1, l1, h2, l2, h3, l3;
                bsplit(eluf(a4[0] + b0), h0, l0);
                bsplit(eluf(a4[1] + b1), h1, l1);
                bsplit(eluf(a4[2] + b0), h2, l2);
                bsplit(eluf(a4[3] + b1), h3, l3);
                if (mode == 0) {
                    if (row < M) {
                        *(__nv_bfloat162*)(CH + (size_t)row * ldc + col) = __nv_bfloat162(h0, h1);
                        *(__nv_bfloat162*)(CL + (size_t)row * ldc + col) = __nv_bfloat162(l0, l1);
                    }
                    if (row + 8 < M) {
                        *(__nv_bfloat162*)(CH + (size_t)(row + 8) * ldc + col) = __nv_bfloat162(h2, h3);
                        *(__nv_bfloat162*)(CL + (size_t)(row + 8) * ldc + col) = __nv_bfloat162(l2, l3);
                    }
                } else {
                    if (row < M) {
                        CH[(size_t)col * ldc + row] = h0;       CL[(size_t)col * ldc + row] = l0;
                        CH[(size_t)(col + 1) * ldc + row] = h1; CL[(size_t)(col + 1) * ldc + row] = l1;
                    }
                    if (row + 8 < M) {
                        CH[(size_t)col * ldc + row + 8] = h2;       CL[(size_t)col * ldc + row + 8] = l2;
                        CH[(size_t)(col + 1) * ldc + row + 8] = h3; CL[(size_t)(col + 1) * ldc + row + 8] = l3;
                    }
                }
            }
        }
    }
}

// =====================================================================
// gemm_ca: A operand is fp32 (probabilities), split to bf16 hi/lo in
// registers after LDS; B pre-split pair. 3-term compensation.
// D[m,n] = sum_k A[m,k] * B[n,k];  out fp32 [m*ldc+n].
// A fp32 smem tile: 128 rows x 128B, group(16B) XOR-swizzled with row&7.
// =====================================================================
__global__ void __launch_bounds__(256, 2) gemm_ca(
    const float* __restrict__ Af,
    const bf16* __restrict__ Bhi, const bf16* __restrict__ Blo,
    float* __restrict__ Cf,
    int M, int K, int lda, int ldb, int ldc,
    size_t sA, size_t sB, size_t sC)
{
    extern __shared__ char smem[];
    const uint32_t sbase = smem_u32(smem);

    const int tid  = threadIdx.x;
    const int wid  = tid >> 5;
    const int lane = tid & 31;
    const int g    = lane >> 3;
    const int r    = lane & 7;
    const int warp_m = wid & 3;
    const int warp_n = wid >> 2;

    const float* A  = Af  + (size_t)blockIdx.z * sA;
    const bf16*  Bh = Bhi + (size_t)blockIdx.z * sB;
    const bf16*  Bl = Blo + (size_t)blockIdx.z * sB;
    const int m0 = blockIdx.y * 128;
    const int n0 = blockIdx.x * 128;

    // B ldmatrix offsets (same as gemm_tc)
    uint32_t boff[4], bswz[4];
    #pragma unroll
    for (int p = 0; p < 4; ++p) {
        int row = warp_n * 64 + p * 16 + (g >> 1) * 8 + r;
        boff[p] = (uint32_t)row * 64;
        bswz[p] = (uint32_t)((row >> 1) & 3);
    }
    const uint32_t bq = (uint32_t)(g & 1);

    // A fragment rows/cols (m16n8k16 layout)
    const int fr = lane >> 2;          // 0..7
    const int fc = (lane & 3) * 2;     // 0,2,4,6

    // staging indices
    const int sr0 = tid >> 2;          // B rows (2 lines/thread)
    const int sq  = tid & 3;
    const int ar0 = tid >> 3;          // A rows (4 lines/thread, rows +32)
    const int ag  = tid & 7;           // A 16B group 0..7

    float acc[2][8][4];
    #pragma unroll
    for (int mt = 0; mt < 2; ++mt)
        #pragma unroll
        for (int nt = 0; nt < 8; ++nt)
            #pragma unroll
            for (int c = 0; c < 4; ++c) acc[mt][nt][c] = 0.0f;

    const int nc = K >> 5;

#define CASTAGE(BUF, K0)                                                         \
    {                                                                            \
        const uint32_t _ab = (uint32_t)(BUF) * 16384u;                           \
        const uint32_t _bb = (uint32_t)(BUF) * 8192u;                            \
        _Pragma("unroll")                                                        \
        for (int q = 0; q < 4; ++q) {                                            \
            int row = ar0 + q * 32;                                              \
            uint32_t d = (uint32_t)row * 128 + (((ag ^ (row & 7)) & 7) << 4);    \
            int m = m0 + row;                                                    \
            size_t ao = (size_t)(m < M ? m : 0) * lda + (K0) + ag * 4;           \
            cp16(sbase + CA_AF + _ab + d, A + ao, m < M);                        \
        }                                                                        \
        _Pragma("unroll")                                                        \
        for (int q = 0; q < 2; ++q) {                                            \
            int row = sr0 + q * 64;                                              \
            uint32_t d = (uint32_t)row * 64 + ((sq ^ ((row >> 1) & 3)) << 4);    \
            size_t bo2 = (size_t)(n0 + row) * ldb + (K0) + sq * 8;               \
            cp16(sbase + CA_BH + _bb + d, Bh + bo2, true);                       \
            cp16(sbase + CA_BL + _bb + d, Bl + bo2, true);                       \
        }                                                                        \
        cp_commit();                                                             \
    }

    CASTAGE(0, 0)
    CASTAGE(1, KC)

    int bi = 0;
    for (int i = 0; i < nc; ++i) {
        asm volatile("cp.async.wait_group 1;" ::: "memory");
        __syncthreads();

        const uint32_t ab  = (uint32_t)bi * 16384u;
        const uint32_t bb  = (uint32_t)bi * 8192u;
        const char* afb = smem + CA_AF + ab;
        const uint32_t bhb = sbase + CA_BH + bb;
        const uint32_t blb = sbase + CA_BL + bb;

        #pragma unroll
        for (int ks = 0; ks < 2; ++ks) {
            // ---- build A fragments from fp32 tile ----
            uint32_t ah[2][4], al[2][4];
            #pragma unroll
            for (int mt = 0; mt < 2; ++mt) {
                const int r1 = warp_m * 32 + mt * 16 + fr;
                const int r2 = r1 + 8;
                const int c0 = ks * 16 + fc;
                #pragma unroll
                for (int half = 0; half < 2; ++half) {   // k and k+8
                    const int c = c0 + half * 8;
                    const uint32_t gidx = (uint32_t)(c >> 2);
                    const uint32_t eoff = (uint32_t)(c & 3) * 4;
                    float2 v0 = *(const float2*)(afb + (uint32_t)r1 * 128 +
                                 (((gidx ^ (r1 & 7)) & 7) << 4) + eoff);
                    float2 v1 = *(const float2*)(afb + (uint32_t)r2 * 128 +
                                 (((gidx ^ (r2 & 7)) & 7) << 4) + eoff);
                    float2 hf0, hf1;
                    ah[mt][half * 2 + 0] = pack_hi(v0, hf0);
                    ah[mt][half * 2 + 1] = pack_hi(v1, hf1);
                    al[mt][half * 2 + 0] = pack_lo(v0, hf0);
                    al[mt][half * 2 + 1] = pack_lo(v1, hf1);
                }
            }
            // ---- B + MMAs (identical structure to gemm_tc) ----
            const uint32_t qb = (uint32_t)(ks * 2) + bq;
            #pragma unroll
            for (int p = 0; p < 4; ++p) {
                uint32_t bhf[4], blf[4];
                const uint32_t o = boff[p] + ((qb ^ bswz[p]) << 4);
                ldsm4(bhf, bhb + o);
                ldsm4(blf, blb + o);
                #pragma unroll
                for (int h2 = 0; h2 < 2; ++h2) {
                    const int nt = p * 2 + h2;
                    #pragma unroll
                    for (int mt = 0; mt < 2; ++mt) {
                        mma_bf16(acc[mt][nt], ah[mt], &bhf[h2 * 2]);  // hi*hi
                        mma_bf16(acc[mt][nt], ah[mt], &blf[h2 * 2]);  // hi*lo
                        mma_bf16(acc[mt][nt], al[mt], &bhf[h2 * 2]);  // lo*hi
                    }
                }
            }
        }

        if (i + 2 < nc) {
            int nb = bi + 2; if (nb >= 3) nb -= 3;
            const int k0 = (i + 2) * KC;
            CASTAGE(nb, k0)
        } else {
            cp_commit();
        }
        if (++bi == 3) bi = 0;
    }
#undef CASTAGE

    // ---- epilogue: fp32 ----
    const int rq = lane >> 2;
    const int cq = (lane & 3) * 2;
    float* C = Cf + (size_t)blockIdx.z * sC;
    #pragma unroll
    for (int mt = 0; mt < 2; ++mt) {
        #pragma unroll
        for (int nt = 0; nt < 8; ++nt) {
            const int row = m0 + warp_m * 32 + mt * 16 + rq;
            const int col = n0 + warp_n * 64 + nt * 8 + cq;
            const float* a4 = acc[mt][nt];
            if (row < M)
                *(float2*)(C + (size_t)row * ldc + col) = make_float2(a4[0], a4[1]);
            if (row + 8 < M)
                *(float2*)(C + (size_t)(row + 8) * ldc + col) = make_float2(a4[2], a4[3]);
        }
    }
}

// =====================================================================
// split fp32 array -> bf16 hi/lo
// =====================================================================
__global__ void __launch_bounds__(256) split_arr(
    const float* __restrict__ src, bf16* __restrict__ hi,
    bf16* __restrict__ lo, int n)
{
    int i = blockIdx.x * 256 + threadIdx.x;
    if (i < n) {
        bf16 h, l;
        bsplit(src[i], h, l);
        hi[i] = h; lo[i] = l;
    }
}

// =====================================================================
// transpose H [B, d, L] -> Ht hi/lo [B, L, d] (bf16 pair)
// =====================================================================
__global__ void __launch_bounds__(256) transpose_hd(
    const float* __restrict__ H, bf16* __restrict__ Hthi, bf16* __restrict__ Htlo)
{
    __shared__ float tile[32][33];
    const int b  = blockIdx.z;
    const int l0 = blockIdx.x * 32, f0 = blockIdx.y * 32;
    const float* src = H + ((size_t)b * DD + f0) * LL + l0;
    for (int r = threadIdx.y; r < 32; r += 8)
        tile[r][threadIdx.x] = src[(size_t)r * LL + threadIdx.x];
    __syncthreads();
    size_t dbase = ((size_t)b * LL + l0) * DD + f0;
    for (int r = threadIdx.y; r < 32; r += 8) {
        bf16 h, l;
        bsplit(tile[threadIdx.x][r], h, l);
        Hthi[dbase + (size_t)r * DD + threadIdx.x] = h;
        Htlo[dbase + (size_t)r * DD + threadIdx.x] = l;
    }
}

// =====================================================================
// Row softmax, fixed row length 4096, fp32 in place (no pair outputs)
// =====================================================================
__global__ void __launch_bounds__(256) softmax4096(float* __restrict__ X)
{
    float* x = X + (size_t)blockIdx.x * 4096;
    const int tid = threadIdx.x;
    const int lane = tid & 31, wid = tid >> 5;
    __shared__ float red[32];

    float4 v[4];
    float mx = -1e30f;
    #pragma unroll
    for (int i = 0; i < 4; ++i) {
        v[i] = *(const float4*)&x[(i * 256 + tid) * 4];
        mx = fmaxf(mx, fmaxf(fmaxf(v[i].x, v[i].y), fmaxf(v[i].z, v[i].w)));
    }
    #pragma unroll
    for (int o = 16; o > 0; o >>= 1) mx = fmaxf(mx, __shfl_xor_sync(0xffffffffu, mx, o));
    if (lane == 0) red[wid] = mx;
    __syncthreads();
    if (wid == 0) {
        float m = (lane < 8) ? red[lane] : -1e30f;
        #pragma unroll
        for (int o = 4; o > 0; o >>= 1) m = fmaxf(m, __shfl_xor_sync(0xffffffffu, m, o));
        if (lane == 0) red[0] = m;
    }
    __syncthreads();
    mx = red[0];

    float sum = 0.0f;
    #pragma unroll
    for (int i = 0; i < 4; ++i) {
        v[i].x = __expf(v[i].x - mx);
        v[i].y = __expf(v[i].y - mx);
        v[i].z = __expf(v[i].z - mx);
        v[i].w = __expf(v[i].w - mx);
        sum += v[i].x + v[i].y + v[i].z + v[i].w;
    }
    #pragma unroll
    for (int o = 16; o > 0; o >>= 1) sum += __shfl_xor_sync(0xffffffffu, sum, o);
    if (lane == 0) red[16 + wid] = sum;
    __syncthreads();
    if (wid == 0) {
        float s = (lane < 8) ? red[16 + lane] : 0.0f;
        #pragma unroll
        for (int o = 4; o > 0; o >>= 1) s += __shfl_xor_sync(0xffffffffu, s, o);
        if (lane == 0) red[16] = s;
    }
    __syncthreads();
    const float inv = 1.0f / red[16];

    #pragma unroll
    for (int i = 0; i < 4; ++i) {
        v[i].x *= inv; v[i].y *= inv; v[i].z *= inv; v[i].w *= inv;
        *(float4*)&x[(i * 256 + tid) * 4] = v[i];
    }
}

// =====================================================================
// Q2b hi/lo = split(Q2[n,:] + C1[b, map[n], :])
// =====================================================================
__global__ void __launch_bounds__(128) q2b_kernel(
    const float* __restrict__ Q2, const int* __restrict__ cmap)
{
    const int n = blockIdx.x;
    const int b = blockIdx.y;
    const int c = cmap[n];
    const float4* q  = (const float4*)(Q2 + (size_t)n * DD);
    const float4* c1 = (const float4*)(g_C1 + ((size_t)b * NC1 + c) * DD);
    const size_t ob = ((size_t)b * NLBL + n) * DD;
    const int i = threadIdx.x;
    float4 a = q[i], bb = c1[i];
    float s0 = a.x + bb.x, s1 = a.y + bb.y, s2 = a.z + bb.z, s3 = a.w + bb.w;
    bf16 h0, l0, h1, l1, h2, l2, h3, l3;
    bsplit(s0, h0, l0); bsplit(s1, h1, l1); bsplit(s2, h2, l2); bsplit(s3, h3, l3);
    *(__nv_bfloat162*)(g_Q2bhi + ob + i * 4)     = __nv_bfloat162(h0, h1);
    *(__nv_bfloat162*)(g_Q2bhi + ob + i * 4 + 2) = __nv_bfloat162(h2, h3);
    *(__nv_bfloat162*)(g_Q2blo + ob + i * 4)     = __nv_bfloat162(l0, l1);
    *(__nv_bfloat162*)(g_Q2blo + ob + i * 4 + 2) = __nv_bfloat162(l2, l3);
}

// =====================================================================
// host
// =====================================================================
extern "C" void kernel_launch(void* const* d_in, const int* in_sizes, int n_in,
                              void* d_out, int out_size)
{
    const float* H    = (const float*)d_in[0];
    const float* Wk   = (const float*)d_in[1];
    const float* bk   = (const float*)d_in[2];
    const float* Wv   = (const float*)d_in[3];
    const float* bv   = (const float*)d_in[4];
    const float* Q1   = (const float*)d_in[5];
    const float* Q2   = (const float*)d_in[6];
    const int*   cmap = (const int*)d_in[7];

    float* C2 = (float*)d_out;                            // [B, Lbl, d]
    float* A2 = C2 + (size_t)BB * NLBL * DD;              // [B, Lbl, L]

    bf16 *pHth, *pHtl, *pKh, *pKl, *pVth, *pVtl;
    bf16 *pQ2bh, *pQ2bl, *pWkh, *pWkl, *pWvh, *pWvl, *pQ1h, *pQ1l;
    float *pE1, *pC1;
    cudaGetSymbolAddress((void**)&pHth,  g_Hthi);
    cudaGetSymbolAddress((void**)&pHtl,  g_Htlo);
    cudaGetSymbolAddress((void**)&pKh,   g_Khi);
    cudaGetSymbolAddress((void**)&pKl,   g_Klo);
    cudaGetSymbolAddress((void**)&pVth,  g_Vthi);
    cudaGetSymbolAddress((void**)&pVtl,  g_Vtlo);
    cudaGetSymbolAddress((void**)&pE1,   g_E1);
    cudaGetSymbolAddress((void**)&pC1,   g_C1);
    cudaGetSymbolAddress((void**)&pQ2bh, g_Q2bhi);
    cudaGetSymbolAddress((void**)&pQ2bl, g_Q2blo);
    cudaGetSymbolAddress((void**)&pWkh,  g_Wkhi);
    cudaGetSymbolAddress((void**)&pWkl,  g_Wklo);
    cudaGetSymbolAddress((void**)&pWvh,  g_Wvhi);
    cudaGetSymbolAddress((void**)&pWvl,  g_Wvlo);
    cudaGetSymbolAddress((void**)&pQ1h,  g_Q1hi);
    cudaGetSymbolAddress((void**)&pQ1l,  g_Q1lo);

    cudaFuncSetAttribute(gemm_tc, cudaFuncAttributeMaxDynamicSharedMemorySize, SM_TOTAL);
    cudaFuncSetAttribute(gemm_ca, cudaFuncAttributeMaxDynamicSharedMemorySize, SM_TOTAL);

    // 0) split weights + Q1
    split_arr<<<(DD * DD + 255) / 256, 256>>>(Wk, pWkh, pWkl, DD * DD);
    split_arr<<<(DD * DD + 255) / 256, 256>>>(Wv, pWvh, pWvl, DD * DD);
    split_arr<<<(NC1 * DD + 255) / 256, 256>>>(Q1, pQ1h, pQ1l, NC1 * DD);

    // 1) Ht pair = transpose(H)
    transpose_hd<<<dim3(LL / 32, DD / 32, BB), dim3(32, 8)>>>(H, pHth, pHtl);

    // 2) K pair = split(elu(Ht Wk^T + bk))  [B,L,d]  (mode 0)
    gemm_tc<<<dim3(DD / 128, LL / 128, BB), 256, SM_TOTAL>>>(
        pHth, pHtl, pWkh, pWkl, (float*)0, pKh, pKl, bk,
        LL, DD, DD, DD, DD, (size_t)LL * DD, 0, (size_t)LL * DD, 1.0f, 0);

    // 3) Vt pair = split(elu(Ht Wv^T + bv))^T  [B,d,L]  (mode 1)
    gemm_tc<<<dim3(DD / 128, LL / 128, BB), 256, SM_TOTAL>>>(
        pHth, pHtl, pWvh, pWvl, (float*)0, pVth, pVtl, bv,
        LL, DD, DD, DD, LL, (size_t)LL * DD, 0, (size_t)DD * LL, 1.0f, 1);

    // 4) E1 = Q1 K^T / SCALE  [B,C1,L] fp32  (mode 2)
    gemm_tc<<<dim3(LL / 128, (NC1 + 127) / 128, BB), 256, SM_TOTAL>>>(
        pQ1h, pQ1l, pKh, pKl, pE1, (bf16*)0, (bf16*)0, bk,
        NC1, DD, DD, DD, LL, 0, (size_t)LL * DD, (size_t)NC1 * LL, SCALE_INV, 2);

    // 5) softmax fp32 in place
    softmax4096<<<BB * NC1, 256>>>(pE1);

    // 6) C1 = A1(fp32) Vt^T  [B,C1,d]  (gemm_ca)
    gemm_ca<<<dim3(DD / 128, (NC1 + 127) / 128, BB), 256, SM_TOTAL>>>(
        pE1, pVth, pVtl, pC1,
        NC1, LL, LL, LL, DD, (size_t)NC1 * LL, (size_t)DD * LL, (size_t)NC1 * DD);

    // 7) Q2b pair = split(Q2 + C1[:, map, :])
    q2b_kernel<<<dim3(NLBL, BB), 128>>>(Q2, cmap);

    // 8) E2 = Q2b K^T / SCALE -> A2 fp32 output region  (mode 2)
    gemm_tc<<<dim3(LL / 128, (NLBL + 127) / 128, BB), 256, SM_TOTAL>>>(
        pQ2bh, pQ2bl, pKh, pKl, A2, (bf16*)0, (bf16*)0, bk,
        NLBL, DD, DD, DD, LL, (size_t)NLBL * DD, (size_t)LL * DD, (size_t)NLBL * LL, SCALE_INV, 2);

    // 9) softmax fp32 in place (this IS the A2 output)
    softmax4096<<<BB * NLBL, 256>>>(A2);

    // 10) C2 = A2(fp32) Vt^T  [B,Lbl,d]  (gemm_ca)
    gemm_ca<<<dim3(DD / 128, (NLBL + 127) / 128, BB), 256, SM_TOTAL>>>(
        A2, pVth, pVtl, C2,
        NLBL, LL, LL, LL, DD, (size_t)NLBL * LL, (size_t)DD * LL, (size_t)NLBL * DD);
}

// round 12
// speedup vs baseline: 1.0459x; 1.0459x over previous
#include <cuda_runtime.h>
#include <cuda_bf16.h>
#include <math.h>
#include <stdint.h>

// Problem dims (fixed)
#define BB   4
#define DD   512
#define LL   4096
#define NC1  1168
#define NLBL 8929

#define SCALE_INV 0.044194173824159216f  // 1/sqrt(512)

#define KC 32   // K elements per chunk (bf16), 64B rows

// smem: 3-stage buffers, each tile 128x32 bf16 = 8KB
#define S_AH 0
#define S_AL 24576
#define S_BH 49152
#define S_BL 73728
#define SM_TOTAL 98304

typedef __nv_bfloat16 bf16;

// ---------------- device scratch ----------------
__device__ bf16  g_Hthi [(size_t)BB * LL * DD];
__device__ bf16  g_Htlo [(size_t)BB * LL * DD];
__device__ bf16  g_Khi  [(size_t)BB * LL * DD];     // [B, L, d]
__device__ bf16  g_Klo  [(size_t)BB * LL * DD];
__device__ bf16  g_Vthi [(size_t)BB * DD * LL];     // [B, d, L]
__device__ bf16  g_Vtlo [(size_t)BB * DD * LL];
__device__ float g_E1   [(size_t)BB * NC1 * LL];    // [B, C1, L]
__device__ bf16  g_A1hi [(size_t)BB * NC1 * LL];
__device__ bf16  g_A1lo [(size_t)BB * NC1 * LL];
__device__ float g_C1   [(size_t)BB * NC1 * DD];    // [B, C1, d]
__device__ bf16  g_Q2bhi[(size_t)BB * NLBL * DD];
__device__ bf16  g_Q2blo[(size_t)BB * NLBL * DD];
__device__ bf16  g_A2hi [(size_t)BB * NLBL * LL];
__device__ bf16  g_A2lo [(size_t)BB * NLBL * LL];
__device__ bf16  g_Wcathi[(size_t)2 * DD * DD];     // [Wk; Wv] rows
__device__ bf16  g_Wcatlo[(size_t)2 * DD * DD];
__device__ float g_bcat  [2 * DD];                  // [bk; bv]
__device__ bf16  g_Q1hi [(size_t)NC1 * DD];
__device__ bf16  g_Q1lo [(size_t)NC1 * DD];

// ---------------- helpers ----------------
__device__ __forceinline__ uint32_t smem_u32(const void* p) {
    uint32_t a;
    asm("{ .reg .u64 t; cvta.to.shared.u64 t, %1; cvt.u32.u64 %0, t; }" : "=r"(a) : "l"(p));
    return a;
}
__device__ __forceinline__ void cp16(uint32_t dst, const void* src, bool pred) {
    int sz = pred ? 16 : 0;
    asm volatile("cp.async.cg.shared.global [%0], [%1], 16, %2;"
                 :: "r"(dst), "l"(src), "r"(sz));
}
__device__ __forceinline__ void cp_commit() {
    asm volatile("cp.async.commit_group;" ::: "memory");
}
__device__ __forceinline__ void ldsm4(uint32_t* r, uint32_t addr) {
    asm volatile("ldmatrix.sync.aligned.m8n8.x4.shared.b16 {%0,%1,%2,%3}, [%4];"
                 : "=r"(r[0]), "=r"(r[1]), "=r"(r[2]), "=r"(r[3]) : "r"(addr));
}
__device__ __forceinline__ void mma_bf16(float* d, const uint32_t* a, const uint32_t* b) {
    asm volatile(
        "mma.sync.aligned.m16n8k16.row.col.f32.bf16.bf16.f32 "
        "{%0,%1,%2,%3}, {%4,%5,%6,%7}, {%8,%9}, {%0,%1,%2,%3};"
        : "+f"(d[0]), "+f"(d[1]), "+f"(d[2]), "+f"(d[3])
        : "r"(a[0]), "r"(a[1]), "r"(a[2]), "r"(a[3]), "r"(b[0]), "r"(b[1]));
}
__device__ __forceinline__ void bsplit(float x, bf16& h, bf16& l) {
    h = __float2bfloat16_rn(x);
    l = __float2bfloat16_rn(x - __bfloat162float(h));
}
__device__ __forceinline__ float eluf(float x) { return x > 0.0f ? x : expm1f(x); }

// =====================================================================
// 3xBF16 mma.sync NT GEMM, 3-stage cp.async pipeline (round-7 mainloop).
// A, B pre-split bf16 hi/lo, K-major.
// mode 0: split(elu(acc+bias[n])) -> Chi/Clo[m*ldc+n]  (bf16)
// mode 1: split(elu(acc+bias[n])) -> Chi/Clo[n*ldc+m]  (bf16, transposed)
// mode 2: Cf[m*ldc+n] = alpha * acc                     (fp32)
// mode 4: fused projection: col<DD -> K-store (mode-0 style, ldc=DD),
//         col>=DD -> Vt transposed store into g_Vthi/g_Vtlo (ld=LL)
// =====================================================================
__global__ void __launch_bounds__(256, 2) gemm_tc(
    const bf16* __restrict__ Ahi, const bf16* __restrict__ Alo,
    const bf16* __restrict__ Bhi, const bf16* __restrict__ Blo,
    float* __restrict__ Cf, bf16* __restrict__ Chi, bf16* __restrict__ Clo,
    const float* __restrict__ bias,
    int M, int K, int lda, int ldb, int ldc,
    size_t sA, size_t sB, size_t sC, float alpha, int mode)
{
    extern __shared__ char smem[];
    const uint32_t sbase = smem_u32(smem);

    const int tid  = threadIdx.x;
    const int wid  = tid >> 5;
    const int lane = tid & 31;
    const int g    = lane >> 3;
    const int r    = lane & 7;
    const int warp_m = wid & 3;
    const int warp_n = wid >> 2;

    const bf16* Ah = Ahi + (size_t)blockIdx.z * sA;
    const bf16* Al = Alo + (size_t)blockIdx.z * sA;
    const bf16* Bh = Bhi + (size_t)blockIdx.z * sB;
    const bf16* Bl = Blo + (size_t)blockIdx.z * sB;
    const int m0 = blockIdx.y * 128;
    const int n0 = blockIdx.x * 128;

    // ldmatrix offsets (64B rows; swizzle: quad ^= (row>>1)&3)
    uint32_t aoff[2], aswz[2], boff[4], bswz[4];
    #pragma unroll
    for (int mt = 0; mt < 2; ++mt) {
        int row = warp_m * 32 + mt * 16 + (g & 1) * 8 + r;
        aoff[mt] = (uint32_t)row * 64;
        aswz[mt] = (uint32_t)((row >> 1) & 3);
    }
    const uint32_t aq = (uint32_t)(g >> 1);
    #pragma unroll
    for (int p = 0; p < 4; ++p) {
        int row = warp_n * 64 + p * 16 + (g >> 1) * 8 + r;
        boff[p] = (uint32_t)row * 64;
        bswz[p] = (uint32_t)((row >> 1) & 3);
    }
    const uint32_t bq = (uint32_t)(g & 1);

    const int sr0 = tid >> 2;
    const int sq  = tid & 3;

    float acc[2][8][4];
    #pragma unroll
    for (int mt = 0; mt < 2; ++mt)
        #pragma unroll
        for (int nt = 0; nt < 8; ++nt)
            #pragma unroll
            for (int c = 0; c < 4; ++c) acc[mt][nt][c] = 0.0f;

    const int nc = K >> 5;

#define STAGE(BUF, K0)                                                           \
    {                                                                            \
        const uint32_t _bo = (uint32_t)(BUF) * 8192u;                            \
        _Pragma("unroll")                                                        \
        for (int q = 0; q < 2; ++q) {                                            \
            int row = sr0 + q * 64;                                              \
            uint32_t d = (uint32_t)row * 64 + ((sq ^ ((row >> 1) & 3)) << 4);    \
            int m = m0 + row;                                                    \
            size_t ao = (size_t)(m < M ? m : 0) * lda + (K0) + sq * 8;           \
            cp16(sbase + S_AH + _bo + d, Ah + ao, m < M);                        \
            cp16(sbase + S_AL + _bo + d, Al + ao, m < M);                        \
            size_t bo2 = (size_t)(n0 + row) * ldb + (K0) + sq * 8;               \
            cp16(sbase + S_BH + _bo + d, Bh + bo2, true);                        \
            cp16(sbase + S_BL + _bo + d, Bl + bo2, true);                        \
        }                                                                        \
        cp_commit();                                                             \
    }

    STAGE(0, 0)
    STAGE(1, KC)

    int bi = 0;
    for (int i = 0; i < nc; ++i) {
        asm volatile("cp.async.wait_group 1;" ::: "memory");
        __syncthreads();

        const uint32_t bo  = (uint32_t)bi * 8192u;
        const uint32_t ahb = sbase + S_AH + bo;
        const uint32_t alb = sbase + S_AL + bo;
        const uint32_t bhb = sbase + S_BH + bo;
        const uint32_t blb = sbase + S_BL + bo;

        #pragma unroll
        for (int ks = 0; ks < 2; ++ks) {
            const uint32_t qa = (uint32_t)(ks * 2) + aq;
            const uint32_t qb = (uint32_t)(ks * 2) + bq;
            uint32_t ah[2][4], al[2][4];
            #pragma unroll
            for (int mt = 0; mt < 2; ++mt) {
                const uint32_t o = aoff[mt] + ((qa ^ aswz[mt]) << 4);
                ldsm4(ah[mt], ahb + o);
                ldsm4(al[mt], alb + o);
            }
            #pragma unroll
            for (int p = 0; p < 4; ++p) {
                uint32_t bhf[4], blf[4];
                const uint32_t o = boff[p] + ((qb ^ bswz[p]) << 4);
                ldsm4(bhf, bhb + o);
                ldsm4(blf, blb + o);
                #pragma unroll
                for (int h2 = 0; h2 < 2; ++h2) {
                    const int nt = p * 2 + h2;
                    #pragma unroll
                    for (int mt = 0; mt < 2; ++mt) {
                        mma_bf16(acc[mt][nt], ah[mt], &bhf[h2 * 2]);  // hi*hi
                        mma_bf16(acc[mt][nt], ah[mt], &blf[h2 * 2]);  // hi*lo
                        mma_bf16(acc[mt][nt], al[mt], &bhf[h2 * 2]);  // lo*hi
                    }
                }
            }
        }

        // stage chunk i+2 into the buffer freed at iteration i-1
        if (i + 2 < nc) {
            int nb = bi + 2; if (nb >= 3) nb -= 3;
            const int k0 = (i + 2) * KC;
            STAGE(nb, k0)
        } else {
            cp_commit();   // empty group keeps wait_group accounting exact
        }
        if (++bi == 3) bi = 0;
    }
#undef STAGE

    // ---- epilogue ----
    const int rq = lane >> 2;
    const int cq = (lane & 3) * 2;
    float* C  = Cf  ? Cf  + (size_t)blockIdx.z * sC : (float*)0;
    bf16*  CH = Chi ? Chi + (size_t)blockIdx.z * sC : (bf16*)0;
    bf16*  CL = Clo ? Clo + (size_t)blockIdx.z * sC : (bf16*)0;
    #pragma unroll
    for (int mt = 0; mt < 2; ++mt) {
        #pragma unroll
        for (int nt = 0; nt < 8; ++nt) {
            const int row = m0 + warp_m * 32 + mt * 16 + rq;
            const int col = n0 + warp_n * 64 + nt * 8 + cq;
            const float* a4 = acc[mt][nt];
            if (mode == 2) {
                if (row < M)
                    *(float2*)(C + (size_t)row * ldc + col) =
                        make_float2(alpha * a4[0], alpha * a4[1]);
                if (row + 8 < M)
                    *(float2*)(C + (size_t)(row + 8) * ldc + col) =
                        make_float2(alpha * a4[2], alpha * a4[3]);
            } else if (mode == 4) {
                // fused K/V projection epilogue (M=LL, always in-range)
                const float b0 = bias[col], b1 = bias[col + 1];
                bf16 h0, l0, h1, l1, h2, l2, h3, l3;
                bsplit(eluf(a4[0] + b0), h0, l0);
                bsplit(eluf(a4[1] + b1), h1, l1);
                bsplit(eluf(a4[2] + b0), h2, l2);
                bsplit(eluf(a4[3] + b1), h3, l3);
                if (col < DD) {
                    // K: [B, L, d] row-major pair
                    bf16* kh = g_Khi + (size_t)blockIdx.z * LL * DD;
                    bf16* kl = g_Klo + (size_t)blockIdx.z * LL * DD;
                    *(__nv_bfloat162*)(kh + (size_t)row * DD + col) = __nv_bfloat162(h0, h1);
                    *(__nv_bfloat162*)(kl + (size_t)row * DD + col) = __nv_bfloat162(l0, l1);
                    *(__nv_bfloat162*)(kh + (size_t)(row + 8) * DD + col) = __nv_bfloat162(h2, h3);
                    *(__nv_bfloat162*)(kl + (size_t)(row + 8) * DD + col) = __nv_bfloat162(l2, l3);
                } else {
                    // Vt: [B, d, L] transposed store
                    const int vc = col - DD;
                    bf16* vh = g_Vthi + (size_t)blockIdx.z * DD * LL;
                    bf16* vl = g_Vtlo + (size_t)blockIdx.z * DD * LL;
                    vh[(size_t)vc * LL + row] = h0;       vl[(size_t)vc * LL + row] = l0;
                    vh[(size_t)(vc + 1) * LL + row] = h1; vl[(size_t)(vc + 1) * LL + row] = l1;
                    vh[(size_t)vc * LL + row + 8] = h2;       vl[(size_t)vc * LL + row + 8] = l2;
                    vh[(size_t)(vc + 1) * LL + row + 8] = h3; vl[(size_t)(vc + 1) * LL + row + 8] = l3;
                }
            } else {
                const float b0 = bias[col], b1 = bias[col + 1];
                bf16 h0, l0, h1, l1, h2, l2, h3, l3;
                bsplit(eluf(a4[0] + b0), h0, l0);
                bsplit(eluf(a4[1] + b1), h1, l1);
                bsplit(eluf(a4[2] + b0), h2, l2);
                bsplit(eluf(a4[3] + b1), h3, l3);
                if (mode == 0) {
                    if (row < M) {
                        *(__nv_bfloat162*)(CH + (size_t)row * ldc + col) = __nv_bfloat162(h0, h1);
                        *(__nv_bfloat162*)(CL + (size_t)row * ldc + col) = __nv_bfloat162(l0, l1);
                    }
                    if (row + 8 < M) {
                        *(__nv_bfloat162*)(CH + (size_t)(row + 8) * ldc + col) = __nv_bfloat162(h2, h3);
                        *(__nv_bfloat162*)(CL + (size_t)(row + 8) * ldc + col) = __nv_bfloat162(l2, l3);
                    }
                } else {  // mode 1: transposed
                    if (row < M) {
                        CH[(size_t)col * ldc + row] = h0;       CL[(size_t)col * ldc + row] = l0;
                        CH[(size_t)(col + 1) * ldc + row] = h1; CL[(size_t)(col + 1) * ldc + row] = l1;
                    }
                    if (row + 8 < M) {
                        CH[(size_t)col * ldc + row + 8] = h2;       CL[(size_t)col * ldc + row + 8] = l2;
                        CH[(size_t)(col + 1) * ldc + row + 8] = h3; CL[(size_t)(col + 1) * ldc + row + 8] = l3;
                    }
                }
            }
        }
    }
}

// =====================================================================
// split fp32 array -> bf16 hi/lo
// =====================================================================
__global__ void __launch_bounds__(256) split_arr(
    const float* __restrict__ src, bf16* __restrict__ hi,
    bf16* __restrict__ lo, int n)
{
    int i = blockIdx.x * 256 + threadIdx.x;
    if (i < n) {
        bf16 h, l;
        bsplit(src[i], h, l);
        hi[i] = h; lo[i] = l;
    }
}

// =====================================================================
// concat biases: g_bcat = [bk; bv]
// =====================================================================
__global__ void __launch_bounds__(1024) concat_bias(
    const float* __restrict__ bk, const float* __restrict__ bv)
{
    int i = threadIdx.x;
    g_bcat[i] = (i < DD) ? bk[i] : bv[i - DD];
}

// =====================================================================
// transpose H [B, d, L] -> Ht hi/lo [B, L, d] (bf16 pair)
// =====================================================================
__global__ void __launch_bounds__(256) transpose_hd(
    const float* __restrict__ H, bf16* __restrict__ Hthi, bf16* __restrict__ Htlo)
{
    __shared__ float tile[32][33];
    const int b  = blockIdx.z;
    const int l0 = blockIdx.x * 32, f0 = blockIdx.y * 32;
    const float* src = H + ((size_t)b * DD + f0) * LL + l0;
    for (int r = threadIdx.y; r < 32; r += 8)
        tile[r][threadIdx.x] = src[(size_t)r * LL + threadIdx.x];
    __syncthreads();
    size_t dbase = ((size_t)b * LL + l0) * DD + f0;
    for (int r = threadIdx.y; r < 32; r += 8) {
        bf16 h, l;
        bsplit(tile[threadIdx.x][r], h, l);
        Hthi[dbase + (size_t)r * DD + threadIdx.x] = h;
        Htlo[dbase + (size_t)r * DD + threadIdx.x] = l;
    }
}

// =====================================================================
// Row softmax (len 4096) -> bf16 hi/lo pair; optional fp32 writeback
// =====================================================================
__global__ void __launch_bounds__(256) softmax4096(
    float* __restrict__ X, bf16* __restrict__ Ohi, bf16* __restrict__ Olo,
    int write_f32)
{
    const size_t rb = (size_t)blockIdx.x * 4096;
    float* x = X + rb;
    const int tid = threadIdx.x;
    const int lane = tid & 31, wid = tid >> 5;
    __shared__ float red[32];

    float4 v[4];
    float mx = -1e30f;
    #pragma unroll
    for (int i = 0; i < 4; ++i) {
        v[i] = *(const float4*)&x[(i * 256 + tid) * 4];
        mx = fmaxf(mx, fmaxf(fmaxf(v[i].x, v[i].y), fmaxf(v[i].z, v[i].w)));
    }
    #pragma unroll
    for (int o = 16; o > 0; o >>= 1) mx = fmaxf(mx, __shfl_xor_sync(0xffffffffu, mx, o));
    if (lane == 0) red[wid] = mx;
    __syncthreads();
    if (wid == 0) {
        float m = (lane < 8) ? red[lane] : -1e30f;
        #pragma unroll
        for (int o = 4; o > 0; o >>= 1) m = fmaxf(m, __shfl_xor_sync(0xffffffffu, m, o));
        if (lane == 0) red[0] = m;
    }
    __syncthreads();
    mx = red[0];

    float sum = 0.0f;
    #pragma unroll
    for (int i = 0; i < 4; ++i) {
        v[i].x = __expf(v[i].x - mx);
        v[i].y = __expf(v[i].y - mx);
        v[i].z = __expf(v[i].z - mx);
        v[i].w = __expf(v[i].w - mx);
        sum += v[i].x + v[i].y + v[i].z + v[i].w;
    }
    #pragma unroll
    for (int o = 16; o > 0; o >>= 1) sum += __shfl_xor_sync(0xffffffffu, sum, o);
    if (lane == 0) red[16 + wid] = sum;
    __syncthreads();
    if (wid == 0) {
        float s = (lane < 8) ? red[16 + lane] : 0.0f;
        #pragma unroll
        for (int o = 4; o > 0; o >>= 1) s += __shfl_xor_sync(0xffffffffu, s, o);
        if (lane == 0) red[16] = s;
    }
    __syncthreads();
    const float inv = 1.0f / red[16];

    #pragma unroll
    for (int i = 0; i < 4; ++i) {
        const int e0 = (i * 256 + tid) * 4;
        v[i].x *= inv; v[i].y *= inv; v[i].z *= inv; v[i].w *= inv;
        if (write_f32) *(float4*)&x[e0] = v[i];
        bf16 h0, l0, h1, l1, h2, l2, h3, l3;
        bsplit(v[i].x, h0, l0); bsplit(v[i].y, h1, l1);
        bsplit(v[i].z, h2, l2); bsplit(v[i].w, h3, l3);
        *(__nv_bfloat162*)(Ohi + rb + e0)     = __nv_bfloat162(h0, h1);
        *(__nv_bfloat162*)(Ohi + rb + e0 + 2) = __nv_bfloat162(h2, h3);
        *(__nv_bfloat162*)(Olo + rb + e0)     = __nv_bfloat162(l0, l1);
        *(__nv_bfloat162*)(Olo + rb + e0 + 2) = __nv_bfloat162(l2, l3);
    }
}

// =====================================================================
// Q2b hi/lo = split(Q2[n,:] + C1[b, map[n], :]) — 2 rows per block
// =====================================================================
__global__ void __launch_bounds__(256) q2b_kernel(
    const float* __restrict__ Q2, const int* __restrict__ cmap)
{
    const int n = blockIdx.x * 2 + (threadIdx.x >> 7);
    if (n >= NLBL) return;
    const int b = blockIdx.y;
    const int c = cmap[n];
    const int i = threadIdx.x & 127;
    const float4* q  = (const float4*)(Q2 + (size_t)n * DD);
    const float4* c1 = (const float4*)(g_C1 + ((size_t)b * NC1 + c) * DD);
    const size_t ob = ((size_t)b * NLBL + n) * DD;
    float4 a = q[i], bb = c1[i];
    float s0 = a.x + bb.x, s1 = a.y + bb.y, s2 = a.z + bb.z, s3 = a.w + bb.w;
    bf16 h0, l0, h1, l1, h2, l2, h3, l3;
    bsplit(s0, h0, l0); bsplit(s1, h1, l1); bsplit(s2, h2, l2); bsplit(s3, h3, l3);
    *(__nv_bfloat162*)(g_Q2bhi + ob + i * 4)     = __nv_bfloat162(h0, h1);
    *(__nv_bfloat162*)(g_Q2bhi + ob + i * 4 + 2) = __nv_bfloat162(h2, h3);
    *(__nv_bfloat162*)(g_Q2blo + ob + i * 4)     = __nv_bfloat162(l0, l1);
    *(__nv_bfloat162*)(g_Q2blo + ob + i * 4 + 2) = __nv_bfloat162(l2, l3);
}

// =====================================================================
// host
// =====================================================================
extern "C" void kernel_launch(void* const* d_in, const int* in_sizes, int n_in,
                              void* d_out, int out_size)
{
    const float* H    = (const float*)d_in[0];
    const float* Wk   = (const float*)d_in[1];
    const float* bk   = (const float*)d_in[2];
    const float* Wv   = (const float*)d_in[3];
    const float* bv   = (const float*)d_in[4];
    const float* Q1   = (const float*)d_in[5];
    const float* Q2   = (const float*)d_in[6];
    const int*   cmap = (const int*)d_in[7];

    float* C2 = (float*)d_out;                            // [B, Lbl, d]
    float* A2 = C2 + (size_t)BB * NLBL * DD;              // [B, Lbl, L]

    bf16 *pHth, *pHtl, *pKh, *pKl, *pVth, *pVtl, *pA1h, *pA1l;
    bf16 *pQ2bh, *pQ2bl, *pA2h, *pA2l, *pWch, *pWcl, *pQ1h, *pQ1l;
    float *pE1, *pC1, *pbcat;
    cudaGetSymbolAddress((void**)&pHth,  g_Hthi);
    cudaGetSymbolAddress((void**)&pHtl,  g_Htlo);
    cudaGetSymbolAddress((void**)&pKh,   g_Khi);
    cudaGetSymbolAddress((void**)&pKl,   g_Klo);
    cudaGetSymbolAddress((void**)&pVth,  g_Vthi);
    cudaGetSymbolAddress((void**)&pVtl,  g_Vtlo);
    cudaGetSymbolAddress((void**)&pE1,   g_E1);
    cudaGetSymbolAddress((void**)&pA1h,  g_A1hi);
    cudaGetSymbolAddress((void**)&pA1l,  g_A1lo);
    cudaGetSymbolAddress((void**)&pC1,   g_C1);
    cudaGetSymbolAddress((void**)&pQ2bh, g_Q2bhi);
    cudaGetSymbolAddress((void**)&pQ2bl, g_Q2blo);
    cudaGetSymbolAddress((void**)&pA2h,  g_A2hi);
    cudaGetSymbolAddress((void**)&pA2l,  g_A2lo);
    cudaGetSymbolAddress((void**)&pWch,  g_Wcathi);
    cudaGetSymbolAddress((void**)&pWcl,  g_Wcatlo);
    cudaGetSymbolAddress((void**)&pbcat, g_bcat);
    cudaGetSymbolAddress((void**)&pQ1h,  g_Q1hi);
    cudaGetSymbolAddress((void**)&pQ1l,  g_Q1lo);

    cudaFuncSetAttribute(gemm_tc, cudaFuncAttributeMaxDynamicSharedMemorySize, SM_TOTAL);

    // 0) split weights (into concatenated [Wk;Wv]) + Q1, concat bias
    split_arr<<<(DD * DD + 255) / 256, 256>>>(Wk, pWch, pWcl, DD * DD);
    split_arr<<<(DD * DD + 255) / 256, 256>>>(Wv, pWch + (size_t)DD * DD,
                                              pWcl + (size_t)DD * DD, DD * DD);
    split_arr<<<(NC1 * DD + 255) / 256, 256>>>(Q1, pQ1h, pQ1l, NC1 * DD);
    concat_bias<<<1, 1024>>>(bk, bv);

    // 1) Ht pair = transpose(H)
    transpose_hd<<<dim3(LL / 32, DD / 32, BB), dim3(32, 8)>>>(H, pHth, pHtl);

    // 2+3) fused K/V projection: N = 2*DD = 1024, mode 4
    gemm_tc<<<dim3(2 * DD / 128, LL / 128, BB), 256, SM_TOTAL>>>(
        pHth, pHtl, pWch, pWcl, (float*)0, (bf16*)0, (bf16*)0, pbcat,
        LL, DD, DD, DD, DD, (size_t)LL * DD, 0, 0, 1.0f, 4);

    // 4) E1 = Q1 K^T / SCALE  [B,C1,L] fp32  (mode 2)
    gemm_tc<<<dim3(LL / 128, (NC1 + 127) / 128, BB), 256, SM_TOTAL>>>(
        pQ1h, pQ1l, pKh, pKl, pE1, (bf16*)0, (bf16*)0, pbcat,
        NC1, DD, DD, DD, LL, 0, (size_t)LL * DD, (size_t)NC1 * LL, SCALE_INV, 2);

    // 5) softmax -> A1 pair (no fp32 writeback)
    softmax4096<<<BB * NC1, 256>>>(pE1, pA1h, pA1l, 0);

    // 6) C1 = A1 Vt^T  [B,C1,d]  (mode 2)
    gemm_tc<<<dim3(DD / 128, (NC1 + 127) / 128, BB), 256, SM_TOTAL>>>(
        pA1h, pA1l, pVth, pVtl, pC1, (bf16*)0, (bf16*)0, pbcat,
        NC1, LL, LL, LL, DD, (size_t)NC1 * LL, (size_t)DD * LL, (size_t)NC1 * DD, 1.0f, 2);

    // 7) Q2b pair = split(Q2 + C1[:, map, :])
    q2b_kernel<<<dim3((NLBL + 1) / 2, BB), 256>>>(Q2, cmap);

    // 8) E2 = Q2b K^T / SCALE -> A2 fp32 output region  (mode 2)
    gemm_tc<<<dim3(LL / 128, (NLBL + 127) / 128, BB), 256, SM_TOTAL>>>(
        pQ2bh, pQ2bl, pKh, pKl, A2, (bf16*)0, (bf16*)0, pbcat,
        NLBL, DD, DD, DD, LL, (size_t)NLBL * DD, (size_t)LL * DD, (size_t)NLBL * LL, SCALE_INV, 2);

    // 9) softmax A2 (fp32 in place for output) + A2 pair for C2 GEMM
    softmax4096<<<BB * NLBL, 256>>>(A2, pA2h, pA2l, 1);

    // 10) C2 = A2 Vt^T  [B,Lbl,d]  (mode 2)
    gemm_tc<<<dim3(DD / 128, (NLBL + 127) / 128, BB), 256, SM_TOTAL>>>(
        pA2h, pA2l, pVth, pVtl, C2, (bf16*)0, (bf16*)0, pbcat,
        NLBL, LL, LL, LL, DD, (size_t)NLBL * LL, (size_t)DD * LL, (size_t)NLBL * DD, 1.0f, 2);
}

// round 17
// speedup vs baseline: 1.0496x; 1.0036x over previous
#include <cuda_runtime.h>
#include <cuda_bf16.h>
#include <math.h>
#include <stdint.h>

// Problem dims (fixed)
#define BB   4
#define DD   512
#define LL   4096
#define NC1  1168
#define NLBL 8929

#define SCALE_INV 0.044194173824159216f  // 1/sqrt(512)

#define KC 32   // K elements per chunk (bf16), 64B rows

// smem: 3-stage buffers, each tile 128x32 bf16 = 8KB
#define S_AH 0
#define S_AL 24576
#define S_BH 49152
#define S_BL 73728
#define SM_TOTAL 98304

typedef __nv_bfloat16 bf16;

// ---------------- device scratch ----------------
__device__ bf16  g_Hthi [(size_t)BB * LL * DD];
__device__ bf16  g_Htlo [(size_t)BB * LL * DD];
__device__ bf16  g_Khi  [(size_t)BB * LL * DD];     // [B, L, d]
__device__ bf16  g_Klo  [(size_t)BB * LL * DD];
__device__ bf16  g_Vthi [(size_t)BB * DD * LL];     // [B, d, L]
__device__ bf16  g_Vtlo [(size_t)BB * DD * LL];
__device__ float g_E1   [(size_t)BB * NC1 * LL];    // [B, C1, L]
__device__ bf16  g_A1hi [(size_t)BB * NC1 * LL];
__device__ bf16  g_A1lo [(size_t)BB * NC1 * LL];
__device__ float g_C1   [(size_t)BB * NC1 * DD];    // [B, C1, d]
__device__ bf16  g_Q2bhi[(size_t)BB * NLBL * DD];
__device__ bf16  g_Q2blo[(size_t)BB * NLBL * DD];
__device__ bf16  g_A2hi [(size_t)BB * NLBL * LL];
__device__ bf16  g_A2lo [(size_t)BB * NLBL * LL];
__device__ bf16  g_Wcathi[(size_t)2 * DD * DD];     // [Wk; Wv] rows
__device__ bf16  g_Wcatlo[(size_t)2 * DD * DD];
__device__ float g_bcat  [2 * DD];                  // [bk; bv]
__device__ bf16  g_Q1hi [(size_t)NC1 * DD];
__device__ bf16  g_Q1lo [(size_t)NC1 * DD];

// ---------------- helpers ----------------
__device__ __forceinline__ uint32_t smem_u32(const void* p) {
    uint32_t a;
    asm("{ .reg .u64 t; cvta.to.shared.u64 t, %1; cvt.u32.u64 %0, t; }" : "=r"(a) : "l"(p));
    return a;
}
__device__ __forceinline__ void cp16(uint32_t dst, const void* src, bool pred) {
    int sz = pred ? 16 : 0;
    asm volatile("cp.async.cg.shared.global [%0], [%1], 16, %2;"
                 :: "r"(dst), "l"(src), "r"(sz));
}
__device__ __forceinline__ void cp_commit() {
    asm volatile("cp.async.commit_group;" ::: "memory");
}
__device__ __forceinline__ void ldsm4(uint32_t* r, uint32_t addr) {
    asm volatile("ldmatrix.sync.aligned.m8n8.x4.shared.b16 {%0,%1,%2,%3}, [%4];"
                 : "=r"(r[0]), "=r"(r[1]), "=r"(r[2]), "=r"(r[3]) : "r"(addr));
}
__device__ __forceinline__ void mma_bf16(float* d, const uint32_t* a, const uint32_t* b) {
    asm volatile(
        "mma.sync.aligned.m16n8k16.row.col.f32.bf16.bf16.f32 "
        "{%0,%1,%2,%3}, {%4,%5,%6,%7}, {%8,%9}, {%0,%1,%2,%3};"
        : "+f"(d[0]), "+f"(d[1]), "+f"(d[2]), "+f"(d[3])
        : "r"(a[0]), "r"(a[1]), "r"(a[2]), "r"(a[3]), "r"(b[0]), "r"(b[1]));
}
__device__ __forceinline__ void bsplit(float x, bf16& h, bf16& l) {
    h = __float2bfloat16_rn(x);
    l = __float2bfloat16_rn(x - __bfloat162float(h));
}
__device__ __forceinline__ uint32_t pack2(bf16 a, bf16 b) {
    __nv_bfloat162 t(a, b);
    return *(uint32_t*)&t;
}
__device__ __forceinline__ float eluf(float x) { return x > 0.0f ? x : expm1f(x); }

// =====================================================================
// 3xBF16 mma.sync NT GEMM, 3-stage cp.async pipeline (round-7 mainloop).
// A, B pre-split bf16 hi/lo, K-major.
// mode 0: split(elu(acc+bias[n])) -> Chi/Clo[m*ldc+n]  (bf16)
// mode 1: split(elu(acc+bias[n])) -> Chi/Clo[n*ldc+m]  (bf16, transposed)
// mode 2: Cf[m*ldc+n] = alpha * acc                     (fp32)
// mode 4: fused projection: col<DD -> K-store, col>=DD -> Vt transposed
// =====================================================================
__global__ void __launch_bounds__(256, 2) gemm_tc(
    const bf16* __restrict__ Ahi, const bf16* __restrict__ Alo,
    const bf16* __restrict__ Bhi, const bf16* __restrict__ Blo,
    float* __restrict__ Cf, bf16* __restrict__ Chi, bf16* __restrict__ Clo,
    const float* __restrict__ bias,
    int M, int K, int lda, int ldb, int ldc,
    size_t sA, size_t sB, size_t sC, float alpha, int mode)
{
    extern __shared__ char smem[];
    const uint32_t sbase = smem_u32(smem);

    const int tid  = threadIdx.x;
    const int wid  = tid >> 5;
    const int lane = tid & 31;
    const int g    = lane >> 3;
    const int r    = lane & 7;
    const int warp_m = wid & 3;
    const int warp_n = wid >> 2;

    const bf16* Ah = Ahi + (size_t)blockIdx.z * sA;
    const bf16* Al = Alo + (size_t)blockIdx.z * sA;
    const bf16* Bh = Bhi + (size_t)blockIdx.z * sB;
    const bf16* Bl = Blo + (size_t)blockIdx.z * sB;
    const int m0 = blockIdx.y * 128;
    const int n0 = blockIdx.x * 128;

    uint32_t aoff[2], aswz[2], boff[4], bswz[4];
    #pragma unroll
    for (int mt = 0; mt < 2; ++mt) {
        int row = warp_m * 32 + mt * 16 + (g & 1) * 8 + r;
        aoff[mt] = (uint32_t)row * 64;
        aswz[mt] = (uint32_t)((row >> 1) & 3);
    }
    const uint32_t aq = (uint32_t)(g >> 1);
    #pragma unroll
    for (int p = 0; p < 4; ++p) {
        int row = warp_n * 64 + p * 16 + (g >> 1) * 8 + r;
        boff[p] = (uint32_t)row * 64;
        bswz[p] = (uint32_t)((row >> 1) & 3);
    }
    const uint32_t bq = (uint32_t)(g & 1);

    const int sr0 = tid >> 2;
    const int sq  = tid & 3;

    float acc[2][8][4];
    #pragma unroll
    for (int mt = 0; mt < 2; ++mt)
        #pragma unroll
        for (int nt = 0; nt < 8; ++nt)
            #pragma unroll
            for (int c = 0; c < 4; ++c) acc[mt][nt][c] = 0.0f;

    const int nc = K >> 5;

#define STAGE(BUF, K0)                                                           \
    {                                                                            \
        const uint32_t _bo = (uint32_t)(BUF) * 8192u;                            \
        _Pragma("unroll")                                                        \
        for (int q = 0; q < 2; ++q) {                                            \
            int row = sr0 + q * 64;                                              \
            uint32_t d = (uint32_t)row * 64 + ((sq ^ ((row >> 1) & 3)) << 4);    \
            int m = m0 + row;                                                    \
            size_t ao = (size_t)(m < M ? m : 0) * lda + (K0) + sq * 8;           \
            cp16(sbase + S_AH + _bo + d, Ah + ao, m < M);                        \
            cp16(sbase + S_AL + _bo + d, Al + ao, m < M);                        \
            size_t bo2 = (size_t)(n0 + row) * ldb + (K0) + sq * 8;               \
            cp16(sbase + S_BH + _bo + d, Bh + bo2, true);                        \
            cp16(sbase + S_BL + _bo + d, Bl + bo2, true);                        \
        }                                                                        \
        cp_commit();                                                             \
    }

    STAGE(0, 0)
    STAGE(1, KC)

    int bi = 0;
    for (int i = 0; i < nc; ++i) {
        asm volatile("cp.async.wait_group 1;" ::: "memory");
        __syncthreads();

        const uint32_t bo  = (uint32_t)bi * 8192u;
        const uint32_t ahb = sbase + S_AH + bo;
        const uint32_t alb = sbase + S_AL + bo;
        const uint32_t bhb = sbase + S_BH + bo;
        const uint32_t blb = sbase + S_BL + bo;

        #pragma unroll
        for (int ks = 0; ks < 2; ++ks) {
            const uint32_t qa = (uint32_t)(ks * 2) + aq;
            const uint32_t qb = (uint32_t)(ks * 2) + bq;
            uint32_t ah[2][4], al[2][4];
            #pragma unroll
            for (int mt = 0; mt < 2; ++mt) {
                const uint32_t o = aoff[mt] + ((qa ^ aswz[mt]) << 4);
                ldsm4(ah[mt], ahb + o);
                ldsm4(al[mt], alb + o);
            }
            #pragma unroll
            for (int p = 0; p < 4; ++p) {
                uint32_t bhf[4], blf[4];
                const uint32_t o = boff[p] + ((qb ^ bswz[p]) << 4);
                ldsm4(bhf, bhb + o);
                ldsm4(blf, blb + o);
                #pragma unroll
                for (int h2 = 0; h2 < 2; ++h2) {
                    const int nt = p * 2 + h2;
                    #pragma unroll
                    for (int mt = 0; mt < 2; ++mt) {
                        mma_bf16(acc[mt][nt], ah[mt], &bhf[h2 * 2]);  // hi*hi
                        mma_bf16(acc[mt][nt], ah[mt], &blf[h2 * 2]);  // hi*lo
                        mma_bf16(acc[mt][nt], al[mt], &bhf[h2 * 2]);  // lo*hi
                    }
                }
            }
        }

        if (i + 2 < nc) {
            int nb = bi + 2; if (nb >= 3) nb -= 3;
            const int k0 = (i + 2) * KC;
            STAGE(nb, k0)
        } else {
            cp_commit();
        }
        if (++bi == 3) bi = 0;
    }
#undef STAGE

    // ---- epilogue ----
    const int rq = lane >> 2;
    const int cq = (lane & 3) * 2;
    float* C  = Cf  ? Cf  + (size_t)blockIdx.z * sC : (float*)0;
    bf16*  CH = Chi ? Chi + (size_t)blockIdx.z * sC : (bf16*)0;
    bf16*  CL = Clo ? Clo + (size_t)blockIdx.z * sC : (bf16*)0;
    #pragma unroll
    for (int mt = 0; mt < 2; ++mt) {
        #pragma unroll
        for (int nt = 0; nt < 8; ++nt) {
            const int row = m0 + warp_m * 32 + mt * 16 + rq;
            const int col = n0 + warp_n * 64 + nt * 8 + cq;
            const float* a4 = acc[mt][nt];
            if (mode == 2) {
                if (row < M)
                    *(float2*)(C + (size_t)row * ldc + col) =
                        make_float2(alpha * a4[0], alpha * a4[1]);
                if (row + 8 < M)
                    *(float2*)(C + (size_t)(row + 8) * ldc + col) =
                        make_float2(alpha * a4[2], alpha * a4[3]);
            } else if (mode == 4) {
                const float b0 = bias[col], b1 = bias[col + 1];
                bf16 h0, l0, h1, l1, h2, l2, h3, l3;
                bsplit(eluf(a4[0] + b0), h0, l0);
                bsplit(eluf(a4[1] + b1), h1, l1);
                bsplit(eluf(a4[2] + b0), h2, l2);
                bsplit(eluf(a4[3] + b1), h3, l3);
                if (col < DD) {
                    bf16* kh = g_Khi + (size_t)blockIdx.z * LL * DD;
                    bf16* kl = g_Klo + (size_t)blockIdx.z * LL * DD;
                    *(__nv_bfloat162*)(kh + (size_t)row * DD + col) = __nv_bfloat162(h0, h1);
                    *(__nv_bfloat162*)(kl + (size_t)row * DD + col) = __nv_bfloat162(l0, l1);
                    *(__nv_bfloat162*)(kh + (size_t)(row + 8) * DD + col) = __nv_bfloat162(h2, h3);
                    *(__nv_bfloat162*)(kl + (size_t)(row + 8) * DD + col) = __nv_bfloat162(l2, l3);
                } else {
                    const int vc = col - DD;
                    bf16* vh = g_Vthi + (size_t)blockIdx.z * DD * LL;
                    bf16* vl = g_Vtlo + (size_t)blockIdx.z * DD * LL;
                    vh[(size_t)vc * LL + row] = h0;       vl[(size_t)vc * LL + row] = l0;
                    vh[(size_t)(vc + 1) * LL + row] = h1; vl[(size_t)(vc + 1) * LL + row] = l1;
                    vh[(size_t)vc * LL + row + 8] = h2;       vl[(size_t)vc * LL + row + 8] = l2;
                    vh[(size_t)(vc + 1) * LL + row + 8] = h3; vl[(size_t)(vc + 1) * LL + row + 8] = l3;
                }
            } else {
                const float b0 = bias[col], b1 = bias[col + 1];
                bf16 h0, l0, h1, l1, h2, l2, h3, l3;
                bsplit(eluf(a4[0] + b0), h0, l0);
                bsplit(eluf(a4[1] + b1), h1, l1);
                bsplit(eluf(a4[2] + b0), h2, l2);
                bsplit(eluf(a4[3] + b1), h3, l3);
                if (mode == 0) {
                    if (row < M) {
                        *(__nv_bfloat162*)(CH + (size_t)row * ldc + col) = __nv_bfloat162(h0, h1);
                        *(__nv_bfloat162*)(CL + (size_t)row * ldc + col) = __nv_bfloat162(l0, l1);
                    }
                    if (row + 8 < M) {
                        *(__nv_bfloat162*)(CH + (size_t)(row + 8) * ldc + col) = __nv_bfloat162(h2, h3);
                        *(__nv_bfloat162*)(CL + (size_t)(row + 8) * ldc + col) = __nv_bfloat162(l2, l3);
                    }
                } else {
                    if (row < M) {
                        CH[(size_t)col * ldc + row] = h0;       CL[(size_t)col * ldc + row] = l0;
                        CH[(size_t)(col + 1) * ldc + row] = h1; CL[(size_t)(col + 1) * ldc + row] = l1;
                    }
                    if (row + 8 < M) {
                        CH[(size_t)col * ldc + row + 8] = h2;       CL[(size_t)col * ldc + row + 8] = l2;
                        CH[(size_t)(col + 1) * ldc + row + 8] = h3; CL[(size_t)(col + 1) * ldc + row + 8] = l3;
                    }
                }
            }
        }
    }
}

// =====================================================================
// prep: one launch replacing Wk-split, Wv-split, Q1-split, concat_bias
// =====================================================================
#define PREP_W   (DD * DD)                 // 262144
#define PREP_Q1  (NC1 * DD)                // 598016
#define PREP_TOT (2 * PREP_W + PREP_Q1 + 2 * DD)
__global__ void __launch_bounds__(256) prep_kernel(
    const float* __restrict__ Wk, const float* __restrict__ Wv,
    const float* __restrict__ bk, const float* __restrict__ bv,
    const float* __restrict__ Q1)
{
    int i = blockIdx.x * 256 + threadIdx.x;
    if (i < PREP_W) {
        bf16 h, l; bsplit(Wk[i], h, l);
        g_Wcathi[i] = h; g_Wcatlo[i] = l;
    } else if (i < 2 * PREP_W) {
        int j = i - PREP_W;
        bf16 h, l; bsplit(Wv[j], h, l);
        g_Wcathi[PREP_W + j] = h; g_Wcatlo[PREP_W + j] = l;
    } else if (i < 2 * PREP_W + PREP_Q1) {
        int j = i - 2 * PREP_W;
        bf16 h, l; bsplit(Q1[j], h, l);
        g_Q1hi[j] = h; g_Q1lo[j] = l;
    } else if (i < PREP_TOT) {
        int j = i - 2 * PREP_W - PREP_Q1;
        g_bcat[j] = (j < DD) ? bk[j] : bv[j - DD];
    }
}

// =====================================================================
// transpose H [B, d, L] -> Ht hi/lo [B, L, d] (bf16 pair)
// =====================================================================
__global__ void __launch_bounds__(256) transpose_hd(
    const float* __restrict__ H, bf16* __restrict__ Hthi, bf16* __restrict__ Htlo)
{
    __shared__ float tile[32][33];
    const int b  = blockIdx.z;
    const int l0 = blockIdx.x * 32, f0 = blockIdx.y * 32;
    const float* src = H + ((size_t)b * DD + f0) * LL + l0;
    for (int r = threadIdx.y; r < 32; r += 8)
        tile[r][threadIdx.x] = src[(size_t)r * LL + threadIdx.x];
    __syncthreads();
    size_t dbase = ((size_t)b * LL + l0) * DD + f0;
    for (int r = threadIdx.y; r < 32; r += 8) {
        bf16 h, l;
        bsplit(tile[threadIdx.x][r], h, l);
        Hthi[dbase + (size_t)r * DD + threadIdx.x] = h;
        Htlo[dbase + (size_t)r * DD + threadIdx.x] = l;
    }
}

// =====================================================================
// Row softmax (len 4096) -> bf16 hi/lo pair; optional fp32 writeback.
// Streaming cache policy: logits read once (__ldcs); fp32 probs never
// re-read (__stcs). Pair outputs keep default policy (re-read by C-GEMM).
// =====================================================================
__global__ void __launch_bounds__(256) softmax4096(
    float* __restrict__ X, bf16* __restrict__ Ohi, bf16* __restrict__ Olo,
    int write_f32)
{
    const size_t rb = (size_t)blockIdx.x * 4096;
    float* x = X + rb;
    const int tid = threadIdx.x;
    const int lane = tid & 31, wid = tid >> 5;
    __shared__ float red[32];

    float4 v[4];
    float mx = -1e30f;
    #pragma unroll
    for (int i = 0; i < 4; ++i) {
        v[i] = __ldcs((const float4*)&x[(i * 256 + tid) * 4]);
        mx = fmaxf(mx, fmaxf(fmaxf(v[i].x, v[i].y), fmaxf(v[i].z, v[i].w)));
    }
    #pragma unroll
    for (int o = 16; o > 0; o >>= 1) mx = fmaxf(mx, __shfl_xor_sync(0xffffffffu, mx, o));
    if (lane == 0) red[wid] = mx;
    __syncthreads();
    if (wid == 0) {
        float m = (lane < 8) ? red[lane] : -1e30f;
        #pragma unroll
        for (int o = 4; o > 0; o >>= 1) m = fmaxf(m, __shfl_xor_sync(0xffffffffu, m, o));
        if (lane == 0) red[0] = m;
    }
    __syncthreads();
    mx = red[0];

    float sum = 0.0f;
    #pragma unroll
    for (int i = 0; i < 4; ++i) {
        v[i].x = __expf(v[i].x - mx);
        v[i].y = __expf(v[i].y - mx);
        v[i].z = __expf(v[i].z - mx);
        v[i].w = __expf(v[i].w - mx);
        sum += v[i].x + v[i].y + v[i].z + v[i].w;
    }
    #pragma unroll
    for (int o = 16; o > 0; o >>= 1) sum += __shfl_xor_sync(0xffffffffu, sum, o);
    if (lane == 0) red[16 + wid] = sum;
    __syncthreads();
    if (wid == 0) {
        float s = (lane < 8) ? red[16 + lane] : 0.0f;
        #pragma unroll
        for (int o = 4; o > 0; o >>= 1) s += __shfl_xor_sync(0xffffffffu, s, o);
        if (lane == 0) red[16] = s;
    }
    __syncthreads();
    const float inv = 1.0f / red[16];

    #pragma unroll
    for (int i = 0; i < 4; ++i) {
        const int e0 = (i * 256 + tid) * 4;
        v[i].x *= inv; v[i].y *= inv; v[i].z *= inv; v[i].w *= inv;
        if (write_f32) __stcs((float4*)&x[e0], v[i]);
        bf16 h0, l0, h1, l1, h2, l2, h3, l3;
        bsplit(v[i].x, h0, l0); bsplit(v[i].y, h1, l1);
        bsplit(v[i].z, h2, l2); bsplit(v[i].w, h3, l3);
        uint2 uh = make_uint2(pack2(h0, h1), pack2(h2, h3));
        uint2 ul = make_uint2(pack2(l0, l1), pack2(l2, l3));
        *(uint2*)(Ohi + rb + e0) = uh;
        *(uint2*)(Olo + rb + e0) = ul;
    }
}

// =====================================================================
// Q2b hi/lo = split(Q2[n,:] + C1[b, map[n], :]) — 2 rows per block
// =====================================================================
__global__ void __launch_bounds__(256) q2b_kernel(
    const float* __restrict__ Q2, const int* __restrict__ cmap)
{
    const int n = blockIdx.x * 2 + (threadIdx.x >> 7);
    if (n >= NLBL) return;
    const int b = blockIdx.y;
    const int c = __ldg(&cmap[n]);
    const int i = threadIdx.x & 127;
    const float4* q  = (const float4*)(Q2 + (size_t)n * DD);
    const float4* c1 = (const float4*)(g_C1 + ((size_t)b * NC1 + c) * DD);
    const size_t ob = ((size_t)b * NLBL + n) * DD;
    float4 a = __ldg(&q[i]), bb = __ldg(&c1[i]);
    float s0 = a.x + bb.x, s1 = a.y + bb.y, s2 = a.z + bb.z, s3 = a.w + bb.w;
    bf16 h0, l0, h1, l1, h2, l2, h3, l3;
    bsplit(s0, h0, l0); bsplit(s1, h1, l1); bsplit(s2, h2, l2); bsplit(s3, h3, l3);
    uint2 uh = make_uint2(pack2(h0, h1), pack2(h2, h3));
    uint2 ul = make_uint2(pack2(l0, l1), pack2(l2, l3));
    *(uint2*)(g_Q2bhi + ob + i * 4) = uh;
    *(uint2*)(g_Q2blo + ob + i * 4) = ul;
}

// =====================================================================
// host
// =====================================================================
extern "C" void kernel_launch(void* const* d_in, const int* in_sizes, int n_in,
                              void* d_out, int out_size)
{
    const float* H    = (const float*)d_in[0];
    const float* Wk   = (const float*)d_in[1];
    const float* bk   = (const float*)d_in[2];
    const float* Wv   = (const float*)d_in[3];
    const float* bv   = (const float*)d_in[4];
    const float* Q1   = (const float*)d_in[5];
    const float* Q2   = (const float*)d_in[6];
    const int*   cmap = (const int*)d_in[7];

    float* C2 = (float*)d_out;                            // [B, Lbl, d]
    float* A2 = C2 + (size_t)BB * NLBL * DD;              // [B, Lbl, L]

    bf16 *pHth, *pHtl, *pKh, *pKl, *pVth, *pVtl, *pA1h, *pA1l;
    bf16 *pQ2bh, *pQ2bl, *pA2h, *pA2l, *pWch, *pWcl, *pQ1h, *pQ1l;
    float *pE1, *pC1, *pbcat;
    cudaGetSymbolAddress((void**)&pHth,  g_Hthi);
    cudaGetSymbolAddress((void**)&pHtl,  g_Htlo);
    cudaGetSymbolAddress((void**)&pKh,   g_Khi);
    cudaGetSymbolAddress((void**)&pKl,   g_Klo);
    cudaGetSymbolAddress((void**)&pVth,  g_Vthi);
    cudaGetSymbolAddress((void**)&pVtl,  g_Vtlo);
    cudaGetSymbolAddress((void**)&pE1,   g_E1);
    cudaGetSymbolAddress((void**)&pA1h,  g_A1hi);
    cudaGetSymbolAddress((void**)&pA1l,  g_A1lo);
    cudaGetSymbolAddress((void**)&pC1,   g_C1);
    cudaGetSymbolAddress((void**)&pQ2bh, g_Q2bhi);
    cudaGetSymbolAddress((void**)&pQ2bl, g_Q2blo);
    cudaGetSymbolAddress((void**)&pA2h,  g_A2hi);
    cudaGetSymbolAddress((void**)&pA2l,  g_A2lo);
    cudaGetSymbolAddress((void**)&pWch,  g_Wcathi);
    cudaGetSymbolAddress((void**)&pWcl,  g_Wcatlo);
    cudaGetSymbolAddress((void**)&pbcat, g_bcat);
    cudaGetSymbolAddress((void**)&pQ1h,  g_Q1hi);
    cudaGetSymbolAddress((void**)&pQ1l,  g_Q1lo);

    cudaFuncSetAttribute(gemm_tc, cudaFuncAttributeMaxDynamicSharedMemorySize, SM_TOTAL);

    // 0) one prep launch: weight splits + Q1 split + bias concat
    prep_kernel<<<(PREP_TOT + 255) / 256, 256>>>(Wk, Wv, bk, bv, Q1);

    // 1) Ht pair = transpose(H)
    transpose_hd<<<dim3(LL / 32, DD / 32, BB), dim3(32, 8)>>>(H, pHth, pHtl);

    // 2+3) fused K/V projection: N = 2*DD = 1024, mode 4
    gemm_tc<<<dim3(2 * DD / 128, LL / 128, BB), 256, SM_TOTAL>>>(
        pHth, pHtl, pWch, pWcl, (float*)0, (bf16*)0, (bf16*)0, pbcat,
        LL, DD, DD, DD, DD, (size_t)LL * DD, 0, 0, 1.0f, 4);

    // 4) E1 = Q1 K^T / SCALE  [B,C1,L] fp32  (mode 2)
    gemm_tc<<<dim3(LL / 128, (NC1 + 127) / 128, BB), 256, SM_TOTAL>>>(
        pQ1h, pQ1l, pKh, pKl, pE1, (bf16*)0, (bf16*)0, pbcat,
        NC1, DD, DD, DD, LL, 0, (size_t)LL * DD, (size_t)NC1 * LL, SCALE_INV, 2);

    // 5) softmax -> A1 pair (no fp32 writeback)
    softmax4096<<<BB * NC1, 256>>>(pE1, pA1h, pA1l, 0);

    // 6) C1 = A1 Vt^T  [B,C1,d]  (mode 2)
    gemm_tc<<<dim3(DD / 128, (NC1 + 127) / 128, BB), 256, SM_TOTAL>>>(
        pA1h, pA1l, pVth, pVtl, pC1, (bf16*)0, (bf16*)0, pbcat,
        NC1, LL, LL, LL, DD, (size_t)NC1 * LL, (size_t)DD * LL, (size_t)NC1 * DD, 1.0f, 2);

    // 7) Q2b pair = split(Q2 + C1[:, map, :])
    q2b_kernel<<<dim3((NLBL + 1) / 2, BB), 256>>>(Q2, cmap);

    // 8) E2 = Q2b K^T / SCALE -> A2 fp32 output region  (mode 2)
    gemm_tc<<<dim3(LL / 128, (NLBL + 127) / 128, BB), 256, SM_TOTAL>>>(
        pQ2bh, pQ2bl, pKh, pKl, A2, (bf16*)0, (bf16*)0, pbcat,
        NLBL, DD, DD, DD, LL, (size_t)NLBL * DD, (size_t)LL * DD, (size_t)NLBL * LL, SCALE_INV, 2);

    // 9) softmax A2 (fp32 in place for output, streaming) + A2 pair
    softmax4096<<<BB * NLBL, 256>>>(A2, pA2h, pA2l, 1);

    // 10) C2 = A2 Vt^T  [B,Lbl,d]  (mode 2)
    gemm_tc<<<dim3(DD / 128, (NLBL + 127) / 128, BB), 256, SM_TOTAL>>>(
        pA2h, pA2l, pVth, pVtl, C2, (bf16*)0, (bf16*)0, pbcat,
        NLBL, LL, LL, LL, DD, (size_t)NLBL * LL, (size_t)DD * LL, (size_t)NLBL * DD, 1.0f, 2);
}